// round 2
// baseline (speedup 1.0000x reference)
#include <cuda_runtime.h>

#define NQ 14
#define NSTATE (1 << NQ)
#define DEPTH 6
#define NTHREADS 512

typedef unsigned long long ull;

// ---------- packed f32x2 helpers (Blackwell) ----------
__device__ __forceinline__ ull pack2(float lo, float hi) {
    ull r; asm("mov.b64 %0, {%1, %2};" : "=l"(r) : "f"(lo), "f"(hi)); return r;
}
__device__ __forceinline__ void unpack2(ull v, float& lo, float& hi) {
    asm("mov.b64 {%0, %1}, %2;" : "=f"(lo), "=f"(hi) : "l"(v));
}
__device__ __forceinline__ ull fma2(ull a, ull b, ull c) {
    ull d; asm("fma.rn.f32x2 %0, %1, %2, %3;" : "=l"(d) : "l"(a), "l"(b), "l"(c)); return d;
}
__device__ __forceinline__ ull mul2(ull a, ull b) {
    ull d; asm("mul.rn.f32x2 %0, %1, %2;" : "=l"(d) : "l"(a), "l"(b)); return d;
}

__device__ __forceinline__ float2 cmulf(float2 a, float2 b) {
    return make_float2(fmaf(a.x, b.x, -a.y * b.y), fmaf(a.x, b.y, a.y * b.x));
}

// RY rotation on local bit G over 32 register-resident complex amps.
// sgn is the coefficient applied to the partner of the k_G==0 slot.
template<int G>
__device__ __forceinline__ void apply_gate(ull (&r)[32], float c, float sgn) {
    const ull cc = pack2(c, c);
    const ull sp = pack2(sgn, sgn);
    const ull sn = pack2(-sgn, -sgn);
#pragma unroll
    for (int k = 0; k < 32; ++k) {
        if ((k & (1 << G)) == 0) {
            const int k2 = k | (1 << G);
            ull u = r[k], v = r[k2];
            r[k]  = fma2(cc, u, mul2(sp, v));
            r[k2] = fma2(cc, v, mul2(sn, u));
        }
    }
}

// Gates on physical bits 0..4. Register slot k holds element t = k ^ lane,
// so the sgn for the k_g==0 slot is (lane_g ? +s : -s).
__device__ __forceinline__ void gates_low(ull (&r)[32], const float2* gate, int l, int lane) {
    float2 cs;
    cs = gate[l*NQ+0]; apply_gate<0>(r, cs.x, ( lane       & 1) ? cs.y : -cs.y);
    cs = gate[l*NQ+1]; apply_gate<1>(r, cs.x, ((lane >> 1) & 1) ? cs.y : -cs.y);
    cs = gate[l*NQ+2]; apply_gate<2>(r, cs.x, ((lane >> 2) & 1) ? cs.y : -cs.y);
    cs = gate[l*NQ+3]; apply_gate<3>(r, cs.x, ((lane >> 3) & 1) ? cs.y : -cs.y);
    cs = gate[l*NQ+4]; apply_gate<4>(r, cs.x, ((lane >> 4) & 1) ? cs.y : -cs.y);
}

// Sweep over physical bits 5..9: idx = (tid&31) | (k<<5) | ((tid>>5)<<10).
__device__ __forceinline__ void sweep_mid(ull* st, const float2* gate, int l, int tid) {
    ull r[32];
    const int ib = (tid & 31) | ((tid >> 5) << 10);
#pragma unroll
    for (int k = 0; k < 32; ++k) r[k] = st[ib | (k << 5)];
    float2 cs;
    cs = gate[l*NQ+5]; apply_gate<0>(r, cs.x, -cs.y);
    cs = gate[l*NQ+6]; apply_gate<1>(r, cs.x, -cs.y);
    cs = gate[l*NQ+7]; apply_gate<2>(r, cs.x, -cs.y);
    cs = gate[l*NQ+8]; apply_gate<3>(r, cs.x, -cs.y);
    cs = gate[l*NQ+9]; apply_gate<4>(r, cs.x, -cs.y);
#pragma unroll
    for (int k = 0; k < 32; ++k) st[ib | (k << 5)] = r[k];
}

// Sweep over physical bits 9..13 span: idx = tid | (k<<9). Gates on bits 10..13
// (local bits 1..4). If `last`, return signed probability partial (sign = bit13).
__device__ __forceinline__ float sweep_hi(ull* st, const float2* gate, int l, int tid, bool last) {
    ull r[32];
    const int ib = tid;  // bits 0..8
#pragma unroll
    for (int k = 0; k < 32; ++k) r[k] = st[ib | (k << 9)];
    float2 cs;
    cs = gate[l*NQ+10]; apply_gate<1>(r, cs.x, -cs.y);
    cs = gate[l*NQ+11]; apply_gate<2>(r, cs.x, -cs.y);
    cs = gate[l*NQ+12]; apply_gate<3>(r, cs.x, -cs.y);
    cs = gate[l*NQ+13]; apply_gate<4>(r, cs.x, -cs.y);
    if (last) {
        float acc = 0.0f;
#pragma unroll
        for (int k = 0; k < 32; ++k) {
            float re, im; unpack2(r[k], re, im);
            float m = fmaf(re, re, im * im);
            acc += (k & 16) ? -m : m;   // bit13 of idx = k bit 4 (wire 0)
        }
        return acc;
    }
#pragma unroll
    for (int k = 0; k < 32; ++k) st[ib | (k << 9)] = r[k];
    return 0.0f;
}

__global__ void __launch_bounds__(NTHREADS, 1)
vqc_kernel(const float* __restrict__ x, const float* __restrict__ freq,
           const float* __restrict__ vp, float* __restrict__ out)
{
    extern __shared__ ull smem[];
    ull*    st   = smem;                         // 16384 complex amps (re,im) packed
    float2* gate = (float2*)(st + NSTATE);       // [DEPTH][14] (cos, sin) by bit position
    float4* vv   = (float4*)(gate + DEPTH * NQ); // per-wire encoding 2-vector, by bit pos
    float*  red  = (float*)(vv + NQ);            // 16 warp partials

    const int tid  = threadIdx.x;
    const int lane = tid & 31;
    const int bs   = blockIdx.x;

    // ---- setup: gate angles (shared across batch) and per-sample encoding vectors ----
    if (tid < DEPTH * NQ) {
        int l = tid / NQ, w = tid - l * NQ;
        int p = NQ - 1 - w;                      // wire w -> bit position p (wire0 = MSB)
        float s, c;
        sincosf(0.5f * vp[tid], &s, &c);
        gate[l * NQ + p] = make_float2(c, s);
    }
    if (tid < NQ) {
        int w = tid, p = NQ - 1 - w;
        float xv = x[bs * NQ + w];
        float s1, c1; sincosf(0.5f * xv, &s1, &c1);
        float s2, c2; sincosf(0.5f * freq[w] * xv, &s2, &c2);
        const float inv = 0.7071067811865476f;
        float a0 = (c1 - s1) * inv, a1 = (c1 + s1) * inv;
        // v = RX(f x) RY(x) H |0> = (c2*a0 - i s2*a1,  c2*a1 - i s2*a0)
        vv[p] = make_float4(c2 * a0, -s2 * a1, c2 * a1, -s2 * a0);
    }
    __syncthreads();

    // dest block for the low sweep: dest = base | (k ^ lane).
    // CNOT-ladder permutation: amp_new[b] = amp_old[b ^ (b>>1)] (Gray map).
    // src(dest) = Sb ^ gray5(k ^ lane) = Csrc ^ gray5(k).
    const int base  = tid << 5;
    const int Sb    = base ^ (base >> 1);
    const int glane = lane ^ (lane >> 1);
    const int Csrc  = Sb ^ glane;

    // ================= Layer 1: build the initial product state directly at the
    // permuted source index (fuses encoding + first ladder), then low gates ====
    {
        ull r[32];
        // high-bit partial product (src bits 5..13 == Sb bits 5..13)
        float2 phi = make_float2(1.0f, 0.0f);
#pragma unroll
        for (int p = 5; p < NQ; ++p) {
            float4 q = vv[p];
            float2 sel = ((Sb >> p) & 1) ? make_float2(q.z, q.w) : make_float2(q.x, q.y);
            phi = cmulf(phi, sel);
        }
        // low 5 src bits for reg k are e ^ gray(k) with e = Csrc & 31:
        // fold e into the doubling tree so all register indices are constants,
        // and seed the tree with phi so no extra multiply pass is needed.
        const int e = Csrc & 31;
        float2 wv0[5], wv1[5];
#pragma unroll
        for (int p = 0; p < 5; ++p) {
            float4 q = vv[p];
            bool eb = (e >> p) & 1;
            wv0[p] = eb ? make_float2(q.z, q.w) : make_float2(q.x, q.y);
            wv1[p] = eb ? make_float2(q.x, q.y) : make_float2(q.z, q.w);
        }
        float2 tmp[32];
        tmp[0] = cmulf(phi, wv0[0]);
        tmp[1] = cmulf(phi, wv1[0]);
#pragma unroll
        for (int p = 1; p < 5; ++p) {
            const int sz = 1 << p;
#pragma unroll
            for (int j = sz - 1; j >= 0; --j) {
                float2 t = tmp[j];
                tmp[j + sz] = cmulf(wv1[p], t);
                tmp[j]      = cmulf(wv0[p], t);
            }
        }
#pragma unroll
        for (int k = 0; k < 32; ++k) {
            const int gk = k ^ (k >> 1);       // compile-time gray(k)
            r[k] = pack2(tmp[gk].x, tmp[gk].y);
        }
        gates_low(r, gate, 0, lane);
#pragma unroll
        for (int k = 0; k < 32; ++k) st[base | (k ^ lane)] = r[k];
    }
    __syncthreads();
    sweep_mid(st, gate, 0, tid);
    __syncthreads();
    sweep_hi(st, gate, 0, tid, false);
    __syncthreads();

    // ================= Layers 2..6 =================
    float acc = 0.0f;
    for (int l = 1; l < DEPTH; ++l) {
        // low sweep with the ladder permutation folded into the load addresses
        {
            ull r[32];
#pragma unroll
            for (int k = 0; k < 32; ++k)
                r[k] = st[Csrc ^ (k ^ (k >> 1))];
            __syncthreads();                    // all permuted reads before any write
            gates_low(r, gate, l, lane);
#pragma unroll
            for (int k = 0; k < 32; ++k) st[base | (k ^ lane)] = r[k];
        }
        __syncthreads();
        sweep_mid(st, gate, l, tid);
        __syncthreads();
        const bool last = (l == DEPTH - 1);
        acc = sweep_hi(st, gate, l, tid, last);
        if (!last) __syncthreads();
    }

    // ---- <Z_0> reduction ----
#pragma unroll
    for (int o = 16; o; o >>= 1) acc += __shfl_xor_sync(0xffffffffu, acc, o);
    if (lane == 0) red[tid >> 5] = acc;
    __syncthreads();
    if (tid == 0) {
        float s = 0.0f;
#pragma unroll
        for (int wgi = 0; wgi < NTHREADS / 32; ++wgi) s += red[wgi];
        out[bs] = s;
    }
}

extern "C" void kernel_launch(void* const* d_in, const int* in_sizes, int n_in,
                              void* d_out, int out_size) {
    const float* x    = (const float*)d_in[0];
    const float* freq = (const float*)d_in[1];
    const float* vp   = (const float*)d_in[2];
    float* out = (float*)d_out;

    const int B = in_sizes[0] / NQ;  // 2048
    const size_t smem = (size_t)NSTATE * 8 + DEPTH * NQ * 8 + NQ * 16 + 64;

    cudaFuncSetAttribute(vqc_kernel, cudaFuncAttributeMaxDynamicSharedMemorySize, (int)smem);
    vqc_kernel<<<B, NTHREADS, smem>>>(x, freq, vp, out);
}

// round 3
// speedup vs baseline: 1.0593x; 1.0593x over previous
#include <cuda_runtime.h>

#define NQ 14
#define NSTATE (1 << NQ)
#define DEPTH 6
#define NTHREADS 512

typedef unsigned long long ull;

// ---------- packed f32x2 helpers (Blackwell) ----------
__device__ __forceinline__ ull pack2(float lo, float hi) {
    ull r; asm("mov.b64 %0, {%1, %2};" : "=l"(r) : "f"(lo), "f"(hi)); return r;
}
__device__ __forceinline__ void unpack2(ull v, float& lo, float& hi) {
    asm("mov.b64 {%0, %1}, %2;" : "=f"(lo), "=f"(hi) : "l"(v));
}
__device__ __forceinline__ ull fma2(ull a, ull b, ull c) {
    ull d; asm("fma.rn.f32x2 %0, %1, %2, %3;" : "=l"(d) : "l"(a), "l"(b), "l"(c)); return d;
}

__device__ __forceinline__ float2 cmulf(float2 a, float2 b) {
    return make_float2(fmaf(a.x, b.x, -a.y * b.y), fmaf(a.x, b.y, a.y * b.x));
}

// RY rotation on local bit G over 32 register-resident complex amps, via the
// 3-shear (lifting) decomposition:  [[c, s],[−s, c]] = S(t)·V(−s)·S(t),
// t = s/(1+c) = tan(a/2):   u += t·v;  v −= s·u;  u += t·v.
// 3 fma2 per pair (was 2 fma2 + 2 mul2). s_signed/t_signed carry the slot sign.
template<int G>
__device__ __forceinline__ void apply_gate(ull (&r)[32], float s_signed, float t_signed) {
    const ull tt = pack2(t_signed, t_signed);
    const ull ns = pack2(-s_signed, -s_signed);
#pragma unroll
    for (int k = 0; k < 32; ++k) {
        if ((k & (1 << G)) == 0) {
            const int k2 = k | (1 << G);
            ull u = r[k], v = r[k2];
            u = fma2(tt, v, u);      // u1 = u + t v
            v = fma2(ns, u, v);      // v' = v - s u1
            u = fma2(tt, v, u);      // u' = u1 + t v'
            r[k]  = u;
            r[k2] = v;
        }
    }
}

// Gates on physical bits 0..4. Register slot k holds element t = k ^ lane,
// so the rotation sign for the k_g==0 slot is (lane_g ? + : -), applied to
// BOTH s and t (they flip together).
__device__ __forceinline__ void gates_low(ull (&r)[32], const float2* gate, int l, int lane) {
    float2 g;
    g = gate[l*NQ+0]; { float sg = ( lane       & 1) ? g.x : -g.x, tg = ( lane       & 1) ? g.y : -g.y; apply_gate<0>(r, sg, tg); }
    g = gate[l*NQ+1]; { float sg = ((lane >> 1) & 1) ? g.x : -g.x, tg = ((lane >> 1) & 1) ? g.y : -g.y; apply_gate<1>(r, sg, tg); }
    g = gate[l*NQ+2]; { float sg = ((lane >> 2) & 1) ? g.x : -g.x, tg = ((lane >> 2) & 1) ? g.y : -g.y; apply_gate<2>(r, sg, tg); }
    g = gate[l*NQ+3]; { float sg = ((lane >> 3) & 1) ? g.x : -g.x, tg = ((lane >> 3) & 1) ? g.y : -g.y; apply_gate<3>(r, sg, tg); }
    g = gate[l*NQ+4]; { float sg = ((lane >> 4) & 1) ? g.x : -g.x, tg = ((lane >> 4) & 1) ? g.y : -g.y; apply_gate<4>(r, sg, tg); }
}

// Sweep over physical bits 5..9: idx = (tid&31) | (k<<5) | ((tid>>5)<<10).
// Slot k's gate-bit equals k_g directly -> sign = (-s, -t).
__device__ __forceinline__ void sweep_mid(ull* st, const float2* gate, int l, int tid) {
    ull r[32];
    const int ib = (tid & 31) | ((tid >> 5) << 10);
#pragma unroll
    for (int k = 0; k < 32; ++k) r[k] = st[ib | (k << 5)];
    float2 g;
    g = gate[l*NQ+5]; apply_gate<0>(r, -g.x, -g.y);
    g = gate[l*NQ+6]; apply_gate<1>(r, -g.x, -g.y);
    g = gate[l*NQ+7]; apply_gate<2>(r, -g.x, -g.y);
    g = gate[l*NQ+8]; apply_gate<3>(r, -g.x, -g.y);
    g = gate[l*NQ+9]; apply_gate<4>(r, -g.x, -g.y);
#pragma unroll
    for (int k = 0; k < 32; ++k) st[ib | (k << 5)] = r[k];
}

// Sweep over physical bits 9..13 span: idx = tid | (k<<9). Gates on bits 10..13
// (local bits 1..4). If `last`, return signed probability partial (sign = bit13).
__device__ __forceinline__ float sweep_hi(ull* st, const float2* gate, int l, int tid, bool last) {
    ull r[32];
    const int ib = tid;  // bits 0..8
#pragma unroll
    for (int k = 0; k < 32; ++k) r[k] = st[ib | (k << 9)];
    float2 g;
    g = gate[l*NQ+10]; apply_gate<1>(r, -g.x, -g.y);
    g = gate[l*NQ+11]; apply_gate<2>(r, -g.x, -g.y);
    g = gate[l*NQ+12]; apply_gate<3>(r, -g.x, -g.y);
    g = gate[l*NQ+13]; apply_gate<4>(r, -g.x, -g.y);
    if (last) {
        float acc = 0.0f;
#pragma unroll
        for (int k = 0; k < 32; ++k) {
            float re, im; unpack2(r[k], re, im);
            float m = fmaf(re, re, im * im);
            acc += (k & 16) ? -m : m;   // bit13 of idx = k bit 4 (wire 0)
        }
        return acc;
    }
#pragma unroll
    for (int k = 0; k < 32; ++k) st[ib | (k << 9)] = r[k];
    return 0.0f;
}

__global__ void __launch_bounds__(NTHREADS, 1)
vqc_kernel(const float* __restrict__ x, const float* __restrict__ freq,
           const float* __restrict__ vp, float* __restrict__ out)
{
    extern __shared__ ull smem[];
    ull*    st   = smem;                         // 16384 complex amps (re,im) packed
    float2* gate = (float2*)(st + NSTATE);       // [DEPTH][14] (sin(θ/2), tan(θ/4)) by bit pos
    float4* vv   = (float4*)(gate + DEPTH * NQ); // per-wire encoding 2-vector, by bit pos
    float*  red  = (float*)(vv + NQ);            // 16 warp partials

    const int tid  = threadIdx.x;
    const int lane = tid & 31;
    const int bs   = blockIdx.x;

    // ---- setup: gate (s, t) table (shared across batch) + per-sample encoding ----
    if (tid < DEPTH * NQ) {
        int l = tid / NQ, w = tid - l * NQ;
        int p = NQ - 1 - w;                      // wire w -> bit position p (wire0 = MSB)
        float s, c;
        sincosf(0.5f * vp[tid], &s, &c);
        gate[l * NQ + p] = make_float2(s, s / (1.0f + c));   // (sin, tan-half)
    }
    if (tid < NQ) {
        int w = tid, p = NQ - 1 - w;
        float xv = x[bs * NQ + w];
        float s1, c1; sincosf(0.5f * xv, &s1, &c1);
        float s2, c2; sincosf(0.5f * freq[w] * xv, &s2, &c2);
        const float inv = 0.7071067811865476f;
        float a0 = (c1 - s1) * inv, a1 = (c1 + s1) * inv;
        // v = RX(f x) RY(x) H |0> = (c2*a0 - i s2*a1,  c2*a1 - i s2*a0)
        vv[p] = make_float4(c2 * a0, -s2 * a1, c2 * a1, -s2 * a0);
    }
    __syncthreads();

    // dest block for the low sweep: dest = base | (k ^ lane).
    // CNOT-ladder permutation: amp_new[b] = amp_old[b ^ (b>>1)] (Gray map).
    // src(dest) = Sb ^ gray5(k ^ lane) = Csrc ^ gray5(k).
    const int base  = tid << 5;
    const int Sb    = base ^ (base >> 1);
    const int glane = lane ^ (lane >> 1);
    const int Csrc  = Sb ^ glane;

    // ================= Layer 1: build the initial product state directly at the
    // permuted source index (fuses encoding + first ladder), then low gates ====
    {
        ull r[32];
        // high-bit partial product (src bits 5..13 == Sb bits 5..13)
        float2 phi = make_float2(1.0f, 0.0f);
#pragma unroll
        for (int p = 5; p < NQ; ++p) {
            float4 q = vv[p];
            float2 sel = ((Sb >> p) & 1) ? make_float2(q.z, q.w) : make_float2(q.x, q.y);
            phi = cmulf(phi, sel);
        }
        // low 5 src bits for reg k are e ^ gray(k) with e = Csrc & 31:
        // fold e into the doubling tree (seeded with phi) so register indices
        // are compile-time constants.
        const int e = Csrc & 31;
        float2 wv0[5], wv1[5];
#pragma unroll
        for (int p = 0; p < 5; ++p) {
            float4 q = vv[p];
            bool eb = (e >> p) & 1;
            wv0[p] = eb ? make_float2(q.z, q.w) : make_float2(q.x, q.y);
            wv1[p] = eb ? make_float2(q.x, q.y) : make_float2(q.z, q.w);
        }
        float2 tmp[32];
        tmp[0] = cmulf(phi, wv0[0]);
        tmp[1] = cmulf(phi, wv1[0]);
#pragma unroll
        for (int p = 1; p < 5; ++p) {
            const int sz = 1 << p;
#pragma unroll
            for (int j = sz - 1; j >= 0; --j) {
                float2 t = tmp[j];
                tmp[j + sz] = cmulf(wv1[p], t);
                tmp[j]      = cmulf(wv0[p], t);
            }
        }
#pragma unroll
        for (int k = 0; k < 32; ++k) {
            const int gk = k ^ (k >> 1);       // compile-time gray(k)
            r[k] = pack2(tmp[gk].x, tmp[gk].y);
        }
        gates_low(r, gate, 0, lane);
#pragma unroll
        for (int k = 0; k < 32; ++k) st[base | (k ^ lane)] = r[k];
    }
    __syncthreads();
    sweep_mid(st, gate, 0, tid);
    __syncthreads();
    sweep_hi(st, gate, 0, tid, false);
    __syncthreads();

    // ================= Layers 2..6 =================
    float acc = 0.0f;
    for (int l = 1; l < DEPTH; ++l) {
        // low sweep with the ladder permutation folded into the load addresses.
        // Gates run register-only, so they execute BEFORE the hazard barrier —
        // compute overlaps barrier-arrival skew; only the stores sit after it.
        {
            ull r[32];
#pragma unroll
            for (int k = 0; k < 32; ++k)
                r[k] = st[Csrc ^ (k ^ (k >> 1))];
            gates_low(r, gate, l, lane);
            __syncthreads();                    // all permuted reads done before any write
#pragma unroll
            for (int k = 0; k < 32; ++k) st[base | (k ^ lane)] = r[k];
        }
        __syncthreads();
        sweep_mid(st, gate, l, tid);
        __syncthreads();
        const bool last = (l == DEPTH - 1);
        acc = sweep_hi(st, gate, l, tid, last);
        if (!last) __syncthreads();
    }

    // ---- <Z_0> reduction ----
#pragma unroll
    for (int o = 16; o; o >>= 1) acc += __shfl_xor_sync(0xffffffffu, acc, o);
    if (lane == 0) red[tid >> 5] = acc;
    __syncthreads();
    if (tid == 0) {
        float s = 0.0f;
#pragma unroll
        for (int wgi = 0; wgi < NTHREADS / 32; ++wgi) s += red[wgi];
        out[bs] = s;
    }
}

extern "C" void kernel_launch(void* const* d_in, const int* in_sizes, int n_in,
                              void* d_out, int out_size) {
    const float* x    = (const float*)d_in[0];
    const float* freq = (const float*)d_in[1];
    const float* vp   = (const float*)d_in[2];
    float* out = (float*)d_out;

    const int B = in_sizes[0] / NQ;  // 2048
    const size_t smem = (size_t)NSTATE * 8 + DEPTH * NQ * 8 + NQ * 16 + 64;

    cudaFuncSetAttribute(vqc_kernel, cudaFuncAttributeMaxDynamicSharedMemorySize, (int)smem);
    vqc_kernel<<<B, NTHREADS, smem>>>(x, freq, vp, out);
}